// round 17
// baseline (speedup 1.0000x reference)
#include <cuda_runtime.h>

// DirectVoxGO volume rendering composite, R13: speculative-front rgb.
//   log2(1-alpha_i) = -interval * log2(1 + exp(density_i + shift))
//   w_i = P_{i-1} - P_i,  P = 2^(per-ray inclusive prefix of log2(1-alpha))
//   out[r] = sum w_i rgb_i + P_last * bg
// Chunk break when log2(T) < -25. rgb loads split:
//   lanes < 16: issued at loop top with density (almost always visible),
//   lanes >= 16: lazy, gated on exact per-lane excl > -25 after the scan.
//
// Kernel 1: offsets table, 16 elements/thread (4 x int4), prev via shfl.
// Kernel 2: one warp per ray, 4 samples/thread, 128-thread blocks.

#define MAX_RAYS ((1 << 20))
__device__ int g_offsets[MAX_RAYS + 2];

__device__ __forceinline__ float f_ex2(float x) {
    float y; asm("ex2.approx.ftz.f32 %0, %1;" : "=f"(y) : "f"(x)); return y;
}
__device__ __forceinline__ float f_lg2(float x) {
    float y; asm("lg2.approx.ftz.f32 %0, %1;" : "=f"(y) : "f"(x)); return y;
}

// ---- Phase 1: offsets table, 16 elements per thread ----
__global__ void __launch_bounds__(256)
build_offsets_vec16(const int* __restrict__ ray_id, int M, int n_rays) {
    const int t  = blockIdx.x * blockDim.x + threadIdx.x;
    const int e0 = t * 16;
    const bool full = (e0 + 15 < M);

    int4 v0 = make_int4(0,0,0,0), v1 = v0, v2 = v0, v3 = v0;
    if (full) {
        const int4* p = reinterpret_cast<const int4*>(ray_id) + t * 4;
        v0 = p[0]; v1 = p[1]; v2 = p[2]; v3 = p[3];
    }
    const int prevw = __shfl_up_sync(0xffffffffu, v3.w, 1);

    if (e0 >= M) return;

    if (!full) {                          // scalar tail (generic-M safety)
        int prev = (e0 == 0) ? -1 : __ldg(&ray_id[e0 - 1]);
        for (int i = e0; i < M; ++i) {
            int cur = __ldg(&ray_id[i]);
            for (int r = prev + 1; r <= cur; ++r) g_offsets[r] = i;
            prev = cur;
        }
        for (int r = prev + 1; r <= n_rays; ++r) g_offsets[r] = M;
        return;
    }

    int prev;
    if ((threadIdx.x & 31) == 0 || e0 == 0)
        prev = (e0 == 0) ? -1 : __ldg(&ray_id[e0 - 1]);
    else
        prev = prevw;

    const int vals[16] = {v0.x, v0.y, v0.z, v0.w,  v1.x, v1.y, v1.z, v1.w,
                          v2.x, v2.y, v2.z, v2.w,  v3.x, v3.y, v3.z, v3.w};
    #pragma unroll
    for (int j = 0; j < 16; ++j) {
        const int cur = vals[j];
        if (cur != prev) {
            for (int r = prev + 1; r <= cur; ++r) g_offsets[r] = e0 + j;
        }
        prev = cur;
    }
    if (e0 + 15 == M - 1) {
        for (int r = prev + 1; r <= n_rays; ++r) g_offsets[r] = M;
    }
}

// ---- Phase 2: one warp per ray, 4 samples/thread, split rgb loads ----
__global__ void __launch_bounds__(128)
composite_kernel(const float* __restrict__ density,
                 const float* __restrict__ rgb,
                 const float* __restrict__ bg,
                 const float* __restrict__ p_shift,
                 const float* __restrict__ p_interval,
                 float* __restrict__ out,
                 int n_rays) {
    const int warp = (blockIdx.x * blockDim.x + threadIdx.x) >> 5;
    const int lane = threadIdx.x & 31;
    if (warp >= n_rays) return;

    const int start = g_offsets[warp];
    const int end   = g_offsets[warp + 1];
    const unsigned seglen = (unsigned)(end - start);

    const float shift = *p_shift;
    const float nInterval = -(*p_interval);
    const float L2E = 1.4426950408889634f;

    float carry = 0.f;                 // running log2(T) at chunk entry
    float ar = 0.f, ag = 0.f, ab = 0.f;

    // aligned chunk base: idx0 = base + lane*4 is always 4-aligned -> LDG.128
    for (int base = (start & ~3); base < end; base += 128) {
        const int idx0 = base + lane * 4;
        const bool grp = (idx0 < end);
        const float* cbase = rgb + 3 * idx0;                      // 16B aligned

        float4 d = make_float4(0.f, 0.f, 0.f, 0.f);
        if (grp) d = *reinterpret_cast<const float4*>(density + idx0);

        // speculative front: lanes < 16 are visible unless the ray saturated
        // before sample 64 of this chunk; loading extra rgb is harmless.
        float4 c0 = make_float4(0.f, 0.f, 0.f, 0.f), c1 = c0, c2 = c0;
        if (grp && lane < 16) {
            c0 = *reinterpret_cast<const float4*>(cbase);
            c1 = *reinterpret_cast<const float4*>(cbase + 4);
            c2 = *reinterpret_cast<const float4*>(cbase + 8);
        }

        // per-element log2(1-alpha); 0 outside [start, end)
        float dv[4] = {d.x, d.y, d.z, d.w};
        float l2t[4];
        #pragma unroll
        for (int j = 0; j < 4; ++j) {
            // single unsigned compare covers idx>=start && idx<end
            const bool in = (unsigned)(idx0 + j - start) < seglen;
            if (in) {
                float e = f_ex2((dv[j] + shift) * L2E);       // exp(x)
                l2t[j] = nInterval * f_lg2(1.f + e);          // <= 0
            } else {
                l2t[j] = 0.f;
            }
        }

        // thread-local inclusive prefix
        const float s0 = l2t[0];
        const float s1 = s0 + l2t[1];
        const float s2 = s1 + l2t[2];
        const float s3 = s2 + l2t[3];

        // warp scan of thread totals
        float inc = s3;
        #pragma unroll
        for (int off = 1; off < 32; off <<= 1) {
            float v = __shfl_up_sync(0xffffffffu, inc, off);
            if (lane >= off) inc += v;
        }
        const float excl = carry + (inc - s3);

        // lazy tail: lanes >= 16 load rgb only if possibly visible
        if (grp && lane >= 16 && excl > -25.0f) {
            c0 = *reinterpret_cast<const float4*>(cbase);
            c1 = *reinterpret_cast<const float4*>(cbase + 4);
            c2 = *reinterpret_cast<const float4*>(cbase + 8);
        }

        // transmittance samples; identical exponents => exact zero weights
        const float Pm1 = f_ex2(excl);
        const float P0  = f_ex2(excl + s0);
        const float P1  = f_ex2(excl + s1);
        const float P2  = f_ex2(excl + s2);
        const float P3  = f_ex2(excl + s3);

        const float w0 = Pm1 - P0;
        const float w1 = P0 - P1;
        const float w2 = P1 - P2;
        const float w3 = P2 - P3;

        // rgb layout: c0=(r0,g0,b0,r1) c1=(g1,b1,r2,g2) c2=(b2,r3,g3,b3)
        ar = fmaf(w0, c0.x, ar);  ag = fmaf(w0, c0.y, ag);  ab = fmaf(w0, c0.z, ab);
        ar = fmaf(w1, c0.w, ar);  ag = fmaf(w1, c1.x, ag);  ab = fmaf(w1, c1.y, ab);
        ar = fmaf(w2, c1.z, ar);  ag = fmaf(w2, c1.w, ag);  ab = fmaf(w2, c2.x, ab);
        ar = fmaf(w3, c2.y, ar);  ag = fmaf(w3, c2.z, ag);  ab = fmaf(w3, c2.w, ab);

        carry += __shfl_sync(0xffffffffu, inc, 31);

        // early ray termination: all remaining weights < 2^-25 (warp-uniform)
        if (carry < -25.0f) break;
    }

    // warp reduction
    #pragma unroll
    for (int off = 16; off; off >>= 1) {
        ar += __shfl_xor_sync(0xffffffffu, ar, off);
        ag += __shfl_xor_sync(0xffffffffu, ag, off);
        ab += __shfl_xor_sync(0xffffffffu, ab, off);
    }

    if (lane == 0) {
        const float Tlast = f_ex2(carry);
        out[3 * warp + 0] = ar + Tlast * bg[0];
        out[3 * warp + 1] = ag + Tlast * bg[1];
        out[3 * warp + 2] = ab + Tlast * bg[2];
    }
}

extern "C" void kernel_launch(void* const* d_in, const int* in_sizes, int n_in,
                              void* d_out, int out_size) {
    const float* density    = (const float*)d_in[0];
    const float* rgb        = (const float*)d_in[1];
    const float* bg         = (const float*)d_in[2];
    const float* p_shift    = (const float*)d_in[3];
    const float* p_interval = (const float*)d_in[4];
    const int*   ray_id     = (const int*)d_in[5];

    const int M      = in_sizes[0];
    const int n_rays = out_size / 3;
    float* out = (float*)d_out;

    {
        const int nthreads16 = (M + 15) / 16;
        const int blocks = (nthreads16 + 255) / 256;
        build_offsets_vec16<<<blocks, 256>>>(ray_id, M, n_rays);
    }
    {
        const int blocks = (n_rays * 32 + 127) / 128;   // 4 rays per block
        composite_kernel<<<blocks, 128>>>(density, rgb, bg, p_shift,
                                          p_interval, out, n_rays);
    }
}